// round 2
// baseline (speedup 1.0000x reference)
#include <cuda_runtime.h>

#define NN 100000
#define EE 1600000
#define HH 64

// Scratch (device globals; no allocation allowed)
__device__ float g_h[NN * HH];
__device__ float g_agg[NN * HH];

__device__ __forceinline__ float frelu(float x) { return x > 0.f ? x : 0.f; }

// ---------------------------------------------------------------------------
// Edge kernel: msg = relu(h[src] + edge_attr); agg[dst] += msg  (float4 atomics)
// 16 threads per edge, each handling one float4 (4 of 64 dims).
// ---------------------------------------------------------------------------
__global__ void __launch_bounds__(256) edge_kernel(
    const float4* __restrict__ h,
    const float4* __restrict__ ea,
    const int* __restrict__ src,
    const int* __restrict__ dst,
    float4* __restrict__ agg)
{
    int t = blockIdx.x * 256 + threadIdx.x;
    int e = t >> 4;
    if (e >= EE) return;
    int c = t & 15;

    int s = __ldg(&src[e]);
    int d = __ldg(&dst[e]);

    float4 a  = ea[(size_t)e * 16 + c];
    float4 hv = __ldg(&h[(size_t)s * 16 + c]);

    float4 m;
    m.x = frelu(a.x + hv.x);
    m.y = frelu(a.y + hv.y);
    m.z = frelu(a.z + hv.z);
    m.w = frelu(a.w + hv.w);

#if defined(__CUDA_ARCH__) && (__CUDA_ARCH__ >= 900)
    atomicAdd(&agg[(size_t)d * 16 + c], m);
#else
    float* ap = (float*)&agg[(size_t)d * 16 + c];
    atomicAdd(ap + 0, m.x);
    atomicAdd(ap + 1, m.y);
    atomicAdd(ap + 2, m.z);
    atomicAdd(ap + 3, m.w);
#endif
}

// ---------------------------------------------------------------------------
// Conv MLP kernel: out = relu_opt(relu(in@W1+b1)@W2+b2) + resid
// Block = 256 threads, 64 nodes/block. Warp handles 8 nodes, lane computes
// output dims (l, l+32). Weights + inputs staged in dynamic shared memory.
// Writes out1 (and optionally out2 = same values, pre-seeding next agg).
// ---------------------------------------------------------------------------
#define MLP_SMEM_FLOATS (4096 + 4096 + 64 + 64 + 64 * 64)
__global__ void __launch_bounds__(256) mlp_kernel(
    const float* __restrict__ in,
    const float* __restrict__ resid,
    const float* __restrict__ W1, const float* __restrict__ b1,
    const float* __restrict__ W2, const float* __restrict__ b2,
    float* __restrict__ out1, float* __restrict__ out2,
    int relu_out)
{
    extern __shared__ float sm[];
    float* sW1 = sm;              // 64*64
    float* sW2 = sm + 4096;       // 64*64
    float* sb1 = sm + 8192;       // 64
    float* sb2 = sm + 8256;       // 64
    float* sIn = sm + 8320;       // 64 nodes * 64

    const int tid = threadIdx.x;
    const int base = blockIdx.x * 64;

    for (int i = tid; i < 4096; i += 256) { sW1[i] = W1[i]; sW2[i] = W2[i]; }
    if (tid < 64) { sb1[tid] = b1[tid]; sb2[tid] = b2[tid]; }
    for (int i = tid; i < 64 * 16; i += 256) {
        int nd = i >> 4, c = i & 15;
        if (base + nd < NN)
            ((float4*)(sIn + nd * 64))[c] = ((const float4*)in)[(size_t)(base + nd) * 16 + c];
    }
    __syncthreads();

    const int w = tid >> 5, l = tid & 31;
    const int ln0 = w * 8;

    float a0[8], a1[8];
#pragma unroll
    for (int j = 0; j < 8; j++) { a0[j] = sb1[l]; a1[j] = sb1[l + 32]; }

#pragma unroll 4
    for (int k = 0; k < 64; k += 2) {
        float w00 = sW1[k * 64 + l],      w01 = sW1[k * 64 + l + 32];
        float w10 = sW1[k * 64 + 64 + l], w11 = sW1[k * 64 + 96 + l];
#pragma unroll
        for (int j = 0; j < 8; j++) {
            float2 v = *(const float2*)&sIn[(ln0 + j) * 64 + k];
            a0[j] = fmaf(v.x, w00, a0[j]); a1[j] = fmaf(v.x, w01, a1[j]);
            a0[j] = fmaf(v.y, w10, a0[j]); a1[j] = fmaf(v.y, w11, a1[j]);
        }
    }

    __syncwarp();
#pragma unroll
    for (int j = 0; j < 8; j++) {
        sIn[(ln0 + j) * 64 + l]      = frelu(a0[j]);
        sIn[(ln0 + j) * 64 + l + 32] = frelu(a1[j]);
    }
    __syncwarp();

#pragma unroll
    for (int j = 0; j < 8; j++) { a0[j] = sb2[l]; a1[j] = sb2[l + 32]; }

#pragma unroll 4
    for (int k = 0; k < 64; k += 2) {
        float w00 = sW2[k * 64 + l],      w01 = sW2[k * 64 + l + 32];
        float w10 = sW2[k * 64 + 64 + l], w11 = sW2[k * 64 + 96 + l];
#pragma unroll
        for (int j = 0; j < 8; j++) {
            float2 v = *(const float2*)&sIn[(ln0 + j) * 64 + k];
            a0[j] = fmaf(v.x, w00, a0[j]); a1[j] = fmaf(v.x, w01, a1[j]);
            a0[j] = fmaf(v.y, w10, a0[j]); a1[j] = fmaf(v.y, w11, a1[j]);
        }
    }

#pragma unroll
    for (int j = 0; j < 8; j++) {
        int nd = base + ln0 + j;
        if (nd < NN) {
            float v0 = a0[j], v1 = a1[j];
            if (relu_out) { v0 = frelu(v0); v1 = frelu(v1); }
            v0 += resid[(size_t)nd * 64 + l];
            v1 += resid[(size_t)nd * 64 + l + 32];
            out1[(size_t)nd * 64 + l] = v0;
            out1[(size_t)nd * 64 + l + 32] = v1;
            if (out2) {
                out2[(size_t)nd * 64 + l] = v0;
                out2[(size_t)nd * 64 + l + 32] = v1;
            }
        }
    }
}

// ---------------------------------------------------------------------------
// Init kernel: h0 = relu(concat(emb[z], t) @ rw1 + rb1) @ rw2 + rb2
// Same structure, input dim 65 (stride 68 in shared for float4/float2 alignment).
// Writes h0 to both g_h and g_agg.
// ---------------------------------------------------------------------------
#define INIT_SMEM_FLOATS (65 * 64 + 4096 + 64 + 64 + 64 * 68)
__global__ void __launch_bounds__(256) init_kernel(
    const int* __restrict__ z,
    const float* __restrict__ t,
    const float* __restrict__ emb,
    const float* __restrict__ W1, const float* __restrict__ b1,
    const float* __restrict__ W2, const float* __restrict__ b2,
    float* __restrict__ out1, float* __restrict__ out2)
{
    extern __shared__ float sm[];
    float* sW1 = sm;                    // 65*64 = 4160
    float* sW2 = sm + 4160;             // 64*64
    float* sb1 = sm + 8256;             // 64
    float* sb2 = sm + 8320;             // 64
    float* sIn = sm + 8384;             // 64 nodes * 68 (65 used)
    __shared__ int sZ[64];

    const int tid = threadIdx.x;
    const int base = blockIdx.x * 64;

    for (int i = tid; i < 4160; i += 256) sW1[i] = W1[i];
    for (int i = tid; i < 4096; i += 256) sW2[i] = W2[i];
    if (tid < 64) {
        sb1[tid] = b1[tid]; sb2[tid] = b2[tid];
        int nd = base + tid;
        sZ[tid] = (nd < NN) ? z[nd] : 0;
        sIn[tid * 68 + 64] = (nd < NN) ? t[nd] : 0.f;
    }
    __syncthreads();

    for (int i = tid; i < 64 * 16; i += 256) {
        int nd = i >> 4, c = i & 15;
        if (base + nd < NN)
            ((float4*)(sIn + nd * 68))[c] = ((const float4*)emb)[(size_t)sZ[nd] * 16 + c];
    }
    __syncthreads();

    const int w = tid >> 5, l = tid & 31;
    const int ln0 = w * 8;

    float a0[8], a1[8];
#pragma unroll
    for (int j = 0; j < 8; j++) { a0[j] = sb1[l]; a1[j] = sb1[l + 32]; }

#pragma unroll 4
    for (int k = 0; k < 64; k += 2) {
        float w00 = sW1[k * 64 + l],      w01 = sW1[k * 64 + l + 32];
        float w10 = sW1[k * 64 + 64 + l], w11 = sW1[k * 64 + 96 + l];
#pragma unroll
        for (int j = 0; j < 8; j++) {
            float2 v = *(const float2*)&sIn[(ln0 + j) * 68 + k];
            a0[j] = fmaf(v.x, w00, a0[j]); a1[j] = fmaf(v.x, w01, a1[j]);
            a0[j] = fmaf(v.y, w10, a0[j]); a1[j] = fmaf(v.y, w11, a1[j]);
        }
    }
    {   // k = 64 tail (the t column)
        float w0 = sW1[64 * 64 + l], w1 = sW1[64 * 64 + l + 32];
#pragma unroll
        for (int j = 0; j < 8; j++) {
            float v = sIn[(ln0 + j) * 68 + 64];
            a0[j] = fmaf(v, w0, a0[j]); a1[j] = fmaf(v, w1, a1[j]);
        }
    }

    __syncwarp();
#pragma unroll
    for (int j = 0; j < 8; j++) {
        sIn[(ln0 + j) * 68 + l]      = frelu(a0[j]);
        sIn[(ln0 + j) * 68 + l + 32] = frelu(a1[j]);
    }
    __syncwarp();

#pragma unroll
    for (int j = 0; j < 8; j++) { a0[j] = sb2[l]; a1[j] = sb2[l + 32]; }

#pragma unroll 4
    for (int k = 0; k < 64; k += 2) {
        float w00 = sW2[k * 64 + l],      w01 = sW2[k * 64 + l + 32];
        float w10 = sW2[k * 64 + 64 + l], w11 = sW2[k * 64 + 96 + l];
#pragma unroll
        for (int j = 0; j < 8; j++) {
            float2 v = *(const float2*)&sIn[(ln0 + j) * 68 + k];
            a0[j] = fmaf(v.x, w00, a0[j]); a1[j] = fmaf(v.x, w01, a1[j]);
            a0[j] = fmaf(v.y, w10, a0[j]); a1[j] = fmaf(v.y, w11, a1[j]);
        }
    }

#pragma unroll
    for (int j = 0; j < 8; j++) {
        int nd = base + ln0 + j;
        if (nd < NN) {
            out1[(size_t)nd * 64 + l] = a0[j];
            out1[(size_t)nd * 64 + l + 32] = a1[j];
            out2[(size_t)nd * 64 + l] = a0[j];
            out2[(size_t)nd * 64 + l + 32] = a1[j];
        }
    }
}

// ---------------------------------------------------------------------------
// Launch
// ---------------------------------------------------------------------------
extern "C" void kernel_launch(void* const* d_in, const int* in_sizes, int n_in,
                              void* d_out, int out_size)
{
    const int*   z    = (const int*)  d_in[0];
    const int*   ei   = (const int*)  d_in[1];   // [2, E]: src = ei, dst = ei + EE
    const float* ea   = (const float*)d_in[2];
    const float* t    = (const float*)d_in[3];
    const float* emb  = (const float*)d_in[4];
    const float* rw1  = (const float*)d_in[5];
    const float* rb1  = (const float*)d_in[6];
    const float* rw2  = (const float*)d_in[7];
    const float* rb2  = (const float*)d_in[8];
    const float* cw1  = (const float*)d_in[9];
    const float* cb1  = (const float*)d_in[10];
    const float* cw2  = (const float*)d_in[11];
    const float* cb2  = (const float*)d_in[12];
    float* out = (float*)d_out;

    float* hp = nullptr;
    float* ap = nullptr;
    cudaGetSymbolAddress((void**)&hp, g_h);
    cudaGetSymbolAddress((void**)&ap, g_agg);

    const int init_smem = INIT_SMEM_FLOATS * sizeof(float);
    const int mlp_smem  = MLP_SMEM_FLOATS * sizeof(float);
    cudaFuncSetAttribute(init_kernel, cudaFuncAttributeMaxDynamicSharedMemorySize, init_smem);
    cudaFuncSetAttribute(mlp_kernel,  cudaFuncAttributeMaxDynamicSharedMemorySize, mlp_smem);

    const int nblk_node = (NN + 63) / 64;
    const int nblk_edge = (EE * 16 + 255) / 256;

    init_kernel<<<nblk_node, 256, init_smem>>>(z, t, emb, rw1, rb1, rw2, rb2, hp, ap);

    for (int li = 0; li < 3; li++) {
        edge_kernel<<<nblk_edge, 256>>>((const float4*)hp, (const float4*)ea,
                                        ei, ei + EE, (float4*)ap);
        const float* W1 = cw1 + li * 4096;
        const float* b1 = cb1 + li * 64;
        const float* W2 = cw2 + li * 4096;
        const float* b2 = cb2 + li * 64;
        if (li < 2) {
            mlp_kernel<<<nblk_node, 256, mlp_smem>>>(ap, hp, W1, b1, W2, b2, hp, ap, 1);
        } else {
            mlp_kernel<<<nblk_node, 256, mlp_smem>>>(ap, hp, W1, b1, W2, b2, out, nullptr, 0);
        }
    }
}

// round 3
// speedup vs baseline: 1.2025x; 1.2025x over previous
#include <cuda_runtime.h>

#define NN 100000
#define EE 1600000
#define HH 64

// Scratch (device globals; no allocation allowed)
__device__ float g_h[NN * HH];
__device__ float g_agg[NN * HH];

__device__ __forceinline__ float frelu(float x) { return x > 0.f ? x : 0.f; }

// ---- packed f32x2 helpers (FFMA2 — only reachable via PTX) -----------------
__device__ __forceinline__ unsigned long long pk2(float lo, float hi) {
    unsigned long long r;
    asm("mov.b64 %0, {%1,%2};" : "=l"(r) : "f"(lo), "f"(hi));
    return r;
}
__device__ __forceinline__ void upk2(unsigned long long v, float& lo, float& hi) {
    asm("mov.b64 {%0,%1}, %2;" : "=f"(lo), "=f"(hi) : "l"(v));
}
__device__ __forceinline__ unsigned long long ffma2(
    unsigned long long a, unsigned long long b, unsigned long long c) {
    unsigned long long d;
    asm("fma.rn.f32x2 %0, %1, %2, %3;" : "=l"(d) : "l"(a), "l"(b), "l"(c));
    return d;
}

// ---------------------------------------------------------------------------
// Edge kernel: msg = relu(h[src] + edge_attr); agg[dst] += msg
// 8 threads/edge, each handles 2 float4 chunks (dims [8c..8c+4) wait: chunks c
// and c+8 of 16). edge_attr read with __ldcs (evict-first) so the 410MB stream
// does not evict the L2-resident h (gather) and agg (atomic RMW) sets.
// ---------------------------------------------------------------------------
__global__ void __launch_bounds__(256) edge_kernel(
    const float4* __restrict__ h,
    const float4* __restrict__ ea,
    const int* __restrict__ src,
    const int* __restrict__ dst,
    float4* __restrict__ agg)
{
    int t = blockIdx.x * 256 + threadIdx.x;
    int e = t >> 3;
    if (e >= EE) return;
    int c = t & 7;

    int s = __ldg(&src[e]);
    int d = __ldg(&dst[e]);

    float4 a0 = __ldcs(&ea[(size_t)e * 16 + c]);
    float4 a1 = __ldcs(&ea[(size_t)e * 16 + c + 8]);
    float4 h0 = __ldg(&h[(size_t)s * 16 + c]);
    float4 h1 = __ldg(&h[(size_t)s * 16 + c + 8]);

    float4 m0, m1;
    m0.x = frelu(a0.x + h0.x); m0.y = frelu(a0.y + h0.y);
    m0.z = frelu(a0.z + h0.z); m0.w = frelu(a0.w + h0.w);
    m1.x = frelu(a1.x + h1.x); m1.y = frelu(a1.y + h1.y);
    m1.z = frelu(a1.z + h1.z); m1.w = frelu(a1.w + h1.w);

    atomicAdd(&agg[(size_t)d * 16 + c], m0);
    atomicAdd(&agg[(size_t)d * 16 + c + 8], m1);
}

// ---------------------------------------------------------------------------
// Conv MLP kernel (FFMA2): out = relu_opt(relu(in@W1+b1)@W2+b2) + resid
// Block = 256 threads = 8 warps, 64 nodes/block (8 nodes/warp as 4 packed
// pairs). Node tile kept TRANSPOSED in smem: sT[k*66 + node] so one LDS.64
// yields a packed (v_j, v_j+1) pair ready for fma.rn.f32x2.
// ---------------------------------------------------------------------------
#define MLP_SMEM_FLOATS (4096 + 4096 + 64 + 64 + 64 * 66)
__global__ void __launch_bounds__(256) mlp_kernel(
    const float* __restrict__ in,
    const float* __restrict__ resid,
    const float* __restrict__ W1, const float* __restrict__ b1,
    const float* __restrict__ W2, const float* __restrict__ b2,
    float* __restrict__ out1, float* __restrict__ out2,
    int relu_out)
{
    extern __shared__ float sm[];
    float* sW1 = sm;              // 64*64
    float* sW2 = sm + 4096;       // 64*64
    float* sb1 = sm + 8192;       // 64
    float* sb2 = sm + 8256;       // 64
    float* sT  = sm + 8320;       // transposed [k][node], stride 66

    const int tid = threadIdx.x;
    const int base = blockIdx.x * 64;

    for (int i = tid; i < 4096; i += 256) { sW1[i] = W1[i]; sW2[i] = W2[i]; }
    if (tid < 64) { sb1[tid] = b1[tid]; sb2[tid] = b2[tid]; }
    for (int i = tid; i < 64 * 16; i += 256) {
        int nd = i >> 4, c = i & 15;
        float4 v = make_float4(0.f, 0.f, 0.f, 0.f);
        if (base + nd < NN) v = ((const float4*)in)[(size_t)(base + nd) * 16 + c];
        sT[(4 * c + 0) * 66 + nd] = v.x;
        sT[(4 * c + 1) * 66 + nd] = v.y;
        sT[(4 * c + 2) * 66 + nd] = v.z;
        sT[(4 * c + 3) * 66 + nd] = v.w;
    }
    __syncthreads();

    const int w = tid >> 5, l = tid & 31;
    const int ln0 = w * 8;

    unsigned long long acc0[4], acc1[4];
    {
        unsigned long long bb0 = pk2(sb1[l], sb1[l]);
        unsigned long long bb1 = pk2(sb1[l + 32], sb1[l + 32]);
#pragma unroll
        for (int p = 0; p < 4; p++) { acc0[p] = bb0; acc1[p] = bb1; }
    }

#pragma unroll 8
    for (int k = 0; k < 64; k++) {
        float w0 = sW1[k * 64 + l];
        float w1 = sW1[k * 64 + l + 32];
        unsigned long long w0p = pk2(w0, w0), w1p = pk2(w1, w1);
        const unsigned long long* vrow = (const unsigned long long*)&sT[k * 66 + ln0];
#pragma unroll
        for (int p = 0; p < 4; p++) {
            unsigned long long vp = vrow[p];
            acc0[p] = ffma2(vp, w0p, acc0[p]);
            acc1[p] = ffma2(vp, w1p, acc1[p]);
        }
    }

    __syncwarp();
#pragma unroll
    for (int p = 0; p < 4; p++) {
        float x0, x1, y0, y1;
        upk2(acc0[p], x0, x1);
        upk2(acc1[p], y0, y1);
        sT[l * 66 + ln0 + 2 * p]            = frelu(x0);
        sT[l * 66 + ln0 + 2 * p + 1]        = frelu(x1);
        sT[(l + 32) * 66 + ln0 + 2 * p]     = frelu(y0);
        sT[(l + 32) * 66 + ln0 + 2 * p + 1] = frelu(y1);
    }
    __syncwarp();

    {
        unsigned long long bb0 = pk2(sb2[l], sb2[l]);
        unsigned long long bb1 = pk2(sb2[l + 32], sb2[l + 32]);
#pragma unroll
        for (int p = 0; p < 4; p++) { acc0[p] = bb0; acc1[p] = bb1; }
    }

#pragma unroll 8
    for (int k = 0; k < 64; k++) {
        float w0 = sW2[k * 64 + l];
        float w1 = sW2[k * 64 + l + 32];
        unsigned long long w0p = pk2(w0, w0), w1p = pk2(w1, w1);
        const unsigned long long* vrow = (const unsigned long long*)&sT[k * 66 + ln0];
#pragma unroll
        for (int p = 0; p < 4; p++) {
            unsigned long long vp = vrow[p];
            acc0[p] = ffma2(vp, w0p, acc0[p]);
            acc1[p] = ffma2(vp, w1p, acc1[p]);
        }
    }

#pragma unroll
    for (int p = 0; p < 4; p++) {
        float x0, x1, y0, y1;
        upk2(acc0[p], x0, x1);
        upk2(acc1[p], y0, y1);
        if (relu_out) { x0 = frelu(x0); x1 = frelu(x1); y0 = frelu(y0); y1 = frelu(y1); }
        int nd0 = base + ln0 + 2 * p;
        int nd1 = nd0 + 1;
        if (nd0 < NN) {
            float v0 = x0 + resid[(size_t)nd0 * 64 + l];
            float v1 = y0 + resid[(size_t)nd0 * 64 + l + 32];
            out1[(size_t)nd0 * 64 + l] = v0;
            out1[(size_t)nd0 * 64 + l + 32] = v1;
            if (out2) { out2[(size_t)nd0 * 64 + l] = v0; out2[(size_t)nd0 * 64 + l + 32] = v1; }
        }
        if (nd1 < NN) {
            float v0 = x1 + resid[(size_t)nd1 * 64 + l];
            float v1 = y1 + resid[(size_t)nd1 * 64 + l + 32];
            out1[(size_t)nd1 * 64 + l] = v0;
            out1[(size_t)nd1 * 64 + l + 32] = v1;
            if (out2) { out2[(size_t)nd1 * 64 + l] = v0; out2[(size_t)nd1 * 64 + l + 32] = v1; }
        }
    }
}

// ---------------------------------------------------------------------------
// Init kernel (FFMA2): h0 = relu(concat(emb[z], t) @ rw1 + rb1) @ rw2 + rb2
// Input dim 65 (t in transposed row 64). Writes h0 to both g_h and g_agg.
// ---------------------------------------------------------------------------
#define INIT_SMEM_FLOATS (65 * 64 + 4096 + 64 + 64 + 65 * 66)
__global__ void __launch_bounds__(256) init_kernel(
    const int* __restrict__ z,
    const float* __restrict__ t,
    const float* __restrict__ emb,
    const float* __restrict__ W1, const float* __restrict__ b1,
    const float* __restrict__ W2, const float* __restrict__ b2,
    float* __restrict__ out1, float* __restrict__ out2)
{
    extern __shared__ float sm[];
    float* sW1 = sm;                    // 65*64 = 4160
    float* sW2 = sm + 4160;             // 64*64
    float* sb1 = sm + 8256;             // 64
    float* sb2 = sm + 8320;             // 64
    float* sT  = sm + 8384;             // transposed [k][node], 65 rows, stride 66
    __shared__ int sZ[64];

    const int tid = threadIdx.x;
    const int base = blockIdx.x * 64;

    for (int i = tid; i < 4160; i += 256) sW1[i] = W1[i];
    for (int i = tid; i < 4096; i += 256) sW2[i] = W2[i];
    if (tid < 64) {
        sb1[tid] = b1[tid]; sb2[tid] = b2[tid];
        int nd = base + tid;
        sZ[tid] = (nd < NN) ? z[nd] : 0;
        sT[64 * 66 + tid] = (nd < NN) ? t[nd] : 0.f;
    }
    __syncthreads();

    for (int i = tid; i < 64 * 16; i += 256) {
        int nd = i >> 4, c = i & 15;
        float4 v = ((const float4*)emb)[(size_t)sZ[nd] * 16 + c];
        sT[(4 * c + 0) * 66 + nd] = v.x;
        sT[(4 * c + 1) * 66 + nd] = v.y;
        sT[(4 * c + 2) * 66 + nd] = v.z;
        sT[(4 * c + 3) * 66 + nd] = v.w;
    }
    __syncthreads();

    const int w = tid >> 5, l = tid & 31;
    const int ln0 = w * 8;

    unsigned long long acc0[4], acc1[4];
    {
        unsigned long long bb0 = pk2(sb1[l], sb1[l]);
        unsigned long long bb1 = pk2(sb1[l + 32], sb1[l + 32]);
#pragma unroll
        for (int p = 0; p < 4; p++) { acc0[p] = bb0; acc1[p] = bb1; }
    }

#pragma unroll 8
    for (int k = 0; k < 65; k++) {
        float w0 = sW1[k * 64 + l];
        float w1 = sW1[k * 64 + l + 32];
        unsigned long long w0p = pk2(w0, w0), w1p = pk2(w1, w1);
        const unsigned long long* vrow = (const unsigned long long*)&sT[k * 66 + ln0];
#pragma unroll
        for (int p = 0; p < 4; p++) {
            unsigned long long vp = vrow[p];
            acc0[p] = ffma2(vp, w0p, acc0[p]);
            acc1[p] = ffma2(vp, w1p, acc1[p]);
        }
    }

    __syncwarp();
#pragma unroll
    for (int p = 0; p < 4; p++) {
        float x0, x1, y0, y1;
        upk2(acc0[p], x0, x1);
        upk2(acc1[p], y0, y1);
        sT[l * 66 + ln0 + 2 * p]            = frelu(x0);
        sT[l * 66 + ln0 + 2 * p + 1]        = frelu(x1);
        sT[(l + 32) * 66 + ln0 + 2 * p]     = frelu(y0);
        sT[(l + 32) * 66 + ln0 + 2 * p + 1] = frelu(y1);
    }
    __syncwarp();

    {
        unsigned long long bb0 = pk2(sb2[l], sb2[l]);
        unsigned long long bb1 = pk2(sb2[l + 32], sb2[l + 32]);
#pragma unroll
        for (int p = 0; p < 4; p++) { acc0[p] = bb0; acc1[p] = bb1; }
    }

#pragma unroll 8
    for (int k = 0; k < 64; k++) {
        float w0 = sW2[k * 64 + l];
        float w1 = sW2[k * 64 + l + 32];
        unsigned long long w0p = pk2(w0, w0), w1p = pk2(w1, w1);
        const unsigned long long* vrow = (const unsigned long long*)&sT[k * 66 + ln0];
#pragma unroll
        for (int p = 0; p < 4; p++) {
            unsigned long long vp = vrow[p];
            acc0[p] = ffma2(vp, w0p, acc0[p]);
            acc1[p] = ffma2(vp, w1p, acc1[p]);
        }
    }

#pragma unroll
    for (int p = 0; p < 4; p++) {
        float x0, x1, y0, y1;
        upk2(acc0[p], x0, x1);
        upk2(acc1[p], y0, y1);
        int nd0 = base + ln0 + 2 * p;
        int nd1 = nd0 + 1;
        if (nd0 < NN) {
            out1[(size_t)nd0 * 64 + l] = x0;
            out1[(size_t)nd0 * 64 + l + 32] = y0;
            out2[(size_t)nd0 * 64 + l] = x0;
            out2[(size_t)nd0 * 64 + l + 32] = y0;
        }
        if (nd1 < NN) {
            out1[(size_t)nd1 * 64 + l] = x1;
            out1[(size_t)nd1 * 64 + l + 32] = y1;
            out2[(size_t)nd1 * 64 + l] = x1;
            out2[(size_t)nd1 * 64 + l + 32] = y1;
        }
    }
}

// ---------------------------------------------------------------------------
// Launch
// ---------------------------------------------------------------------------
extern "C" void kernel_launch(void* const* d_in, const int* in_sizes, int n_in,
                              void* d_out, int out_size)
{
    const int*   z    = (const int*)  d_in[0];
    const int*   ei   = (const int*)  d_in[1];   // [2, E]: src = ei, dst = ei + EE
    const float* ea   = (const float*)d_in[2];
    const float* t    = (const float*)d_in[3];
    const float* emb  = (const float*)d_in[4];
    const float* rw1  = (const float*)d_in[5];
    const float* rb1  = (const float*)d_in[6];
    const float* rw2  = (const float*)d_in[7];
    const float* rb2  = (const float*)d_in[8];
    const float* cw1  = (const float*)d_in[9];
    const float* cb1  = (const float*)d_in[10];
    const float* cw2  = (const float*)d_in[11];
    const float* cb2  = (const float*)d_in[12];
    float* out = (float*)d_out;

    float* hp = nullptr;
    float* ap = nullptr;
    cudaGetSymbolAddress((void**)&hp, g_h);
    cudaGetSymbolAddress((void**)&ap, g_agg);

    const int init_smem = INIT_SMEM_FLOATS * sizeof(float);
    const int mlp_smem  = MLP_SMEM_FLOATS * sizeof(float);
    cudaFuncSetAttribute(init_kernel, cudaFuncAttributeMaxDynamicSharedMemorySize, init_smem);
    cudaFuncSetAttribute(mlp_kernel,  cudaFuncAttributeMaxDynamicSharedMemorySize, mlp_smem);

    const int nblk_node = (NN + 63) / 64;
    const int nblk_edge = (EE * 8 + 255) / 256;

    init_kernel<<<nblk_node, 256, init_smem>>>(z, t, emb, rw1, rb1, rw2, rb2, hp, ap);

    for (int li = 0; li < 3; li++) {
        edge_kernel<<<nblk_edge, 256>>>((const float4*)hp, (const float4*)ea,
                                        ei, ei + EE, (float4*)ap);
        const float* W1 = cw1 + li * 4096;
        const float* b1 = cb1 + li * 64;
        const float* W2 = cw2 + li * 4096;
        const float* b2 = cb2 + li * 64;
        if (li < 2) {
            mlp_kernel<<<nblk_node, 256, mlp_smem>>>(ap, hp, W1, b1, W2, b2, hp, ap, 1);
        } else {
            mlp_kernel<<<nblk_node, 256, mlp_smem>>>(ap, hp, W1, b1, W2, b2, out, nullptr, 0);
        }
    }
}